// round 2
// baseline (speedup 1.0000x reference)
#include <cuda_runtime.h>
#include <float.h>

#define N_TOKENS 65536
#define DIM      256
#define NCODES   4096

#define TM 128
#define TN 128
#define TK 32

// Scratch: 0.5 * ||e_k||^2 per codebook row (device global => no allocation)
__device__ float g_half_enorm[NCODES];

// ---------------------------------------------------------------------------
// Pre-kernel: half squared norms of embedding rows. One warp per row.
// ---------------------------------------------------------------------------
__global__ void enorm_kernel(const float* __restrict__ e) {
    int row  = blockIdx.x * 8 + (threadIdx.x >> 5);
    int lane = threadIdx.x & 31;
    const float4* ep = (const float4*)(e + (size_t)row * DIM);
    float s = 0.f;
    #pragma unroll
    for (int j = lane; j < DIM / 4; j += 32) {
        float4 v = ep[j];
        s += v.x * v.x + v.y * v.y + v.z * v.z + v.w * v.w;
    }
    #pragma unroll
    for (int o = 16; o; o >>= 1) s += __shfl_xor_sync(0xffffffffu, s, o);
    if (lane == 0) g_half_enorm[row] = 0.5f * s;
}

// ---------------------------------------------------------------------------
// Main fused kernel: per 128-token tile, scan all 4096 codes in 128-wide
// tiles; score = z.e - 0.5||e||^2 accumulated in fp32; track (max, min-idx);
// epilogue gathers winning embedding rows and writes indices.
// ---------------------------------------------------------------------------
__global__ __launch_bounds__(256, 2)
void vq_kernel(const float* __restrict__ z,
               const float* __restrict__ e,
               float* __restrict__ out_q,
               float* __restrict__ out_idx)
{
    __shared__ float sA[TM][TK + 1];   // z tile, m-major, pad 1
    __shared__ float sB[TN][TK + 1];   // e tile, n-major, pad 1
    __shared__ int   s_best[TM];

    const int tid = threadIdx.x;
    const int tx  = tid & 15;          // column-thread  0..15
    const int ty  = tid >> 4;          // row-thread     0..15
    const int m0  = blockIdx.x * TM;

    float acc[8][8];
    float best_val[8];
    int   best_idx[8];
    #pragma unroll
    for (int i = 0; i < 8; i++) {
        best_val[i] = -FLT_MAX;
        best_idx[i] = 0x7fffffff;
        #pragma unroll
        for (int j = 0; j < 8; j++) acc[i][j] = 0.f;
    }

    const int lr = tid >> 3;   // 0..31 : row within 32-row pass
    const int c4 = tid & 7;    // float4 slot along K

    for (int n0 = 0; n0 < NCODES; n0 += TN) {
        // ---- K loop: accumulate 128x128 score tile ----
        for (int k0 = 0; k0 < DIM; k0 += TK) {
            // load z tile (coalesced float4, conflict-free scalar smem stores)
            #pragma unroll
            for (int rr = 0; rr < 4; rr++) {
                int row = lr + rr * 32;
                float4 v = *(const float4*)&z[(size_t)(m0 + row) * DIM + k0 + c4 * 4];
                sA[row][c4 * 4 + 0] = v.x;
                sA[row][c4 * 4 + 1] = v.y;
                sA[row][c4 * 4 + 2] = v.z;
                sA[row][c4 * 4 + 3] = v.w;
            }
            // load e tile
            #pragma unroll
            for (int rr = 0; rr < 4; rr++) {
                int row = lr + rr * 32;
                float4 v = *(const float4*)&e[(size_t)(n0 + row) * DIM + k0 + c4 * 4];
                sB[row][c4 * 4 + 0] = v.x;
                sB[row][c4 * 4 + 1] = v.y;
                sB[row][c4 * 4 + 2] = v.z;
                sB[row][c4 * 4 + 3] = v.w;
            }
            __syncthreads();

            #pragma unroll 4
            for (int kk = 0; kk < TK; kk++) {
                float af[8], bf[8];
                #pragma unroll
                for (int i = 0; i < 4; i++) {
                    af[i]     = sA[ty * 4 + i][kk];
                    af[i + 4] = sA[64 + ty * 4 + i][kk];
                }
                #pragma unroll
                for (int j = 0; j < 4; j++) {
                    bf[j]     = sB[tx * 4 + j][kk];
                    bf[j + 4] = sB[64 + tx * 4 + j][kk];
                }
                #pragma unroll
                for (int i = 0; i < 8; i++)
                    #pragma unroll
                    for (int j = 0; j < 8; j++)
                        acc[i][j] += af[i] * bf[j];
            }
            __syncthreads();
        }

        // ---- epilogue for this code tile: score & running argmax ----
        #pragma unroll
        for (int j = 0; j < 8; j++) {
            int col = n0 + ((j < 4) ? (tx * 4 + j) : (64 + tx * 4 + (j - 4)));
            float he = __ldg(&g_half_enorm[col]);
            #pragma unroll
            for (int i = 0; i < 8; i++) {
                float t = acc[i][j] - he;
                if (t > best_val[i] || (t == best_val[i] && col < best_idx[i])) {
                    best_val[i] = t;
                    best_idx[i] = col;
                }
                acc[i][j] = 0.f;
            }
        }
    }

    // ---- reduce across the 16 column-threads (same ty) via shfl ----
    #pragma unroll
    for (int o = 8; o; o >>= 1) {
        #pragma unroll
        for (int i = 0; i < 8; i++) {
            float ov = __shfl_xor_sync(0xffffffffu, best_val[i], o);
            int   oi = __shfl_xor_sync(0xffffffffu, best_idx[i], o);
            if (ov > best_val[i] || (ov == best_val[i] && oi < best_idx[i])) {
                best_val[i] = ov;
                best_idx[i] = oi;
            }
        }
    }
    if (tx == 0) {
        #pragma unroll
        for (int i = 0; i < 4; i++) {
            s_best[ty * 4 + i]      = best_idx[i];
            s_best[64 + ty * 4 + i] = best_idx[4 + i];
        }
    }
    __syncthreads();

    // ---- gather winning embedding rows -> out_q (float4, coalesced) ----
    for (int i4 = tid; i4 < TM * (DIM / 4); i4 += 256) {
        int r = i4 >> 6;          // token row in tile
        int c = i4 & 63;          // float4 within row
        int code = s_best[r];
        ((float4*)out_q)[(size_t)(m0 + r) * (DIM / 4) + c] =
            ((const float4*)e)[(size_t)code * (DIM / 4) + c];
    }
    if (out_idx && tid < TM) out_idx[m0 + tid] = (float)s_best[tid];
}

// ---------------------------------------------------------------------------
extern "C" void kernel_launch(void* const* d_in, const int* in_sizes, int n_in,
                              void* d_out, int out_size)
{
    const float* z = (const float*)d_in[0];
    const float* e = (const float*)d_in[1];
    // guard against input-order surprises
    if (n_in >= 2 && in_sizes[0] == NCODES * DIM && in_sizes[1] == N_TOKENS * DIM) {
        const float* t = z; z = e; e = t;
    }

    float* out = (float*)d_out;
    float* out_idx = (out_size >= N_TOKENS * DIM + N_TOKENS)
                         ? (out + (size_t)N_TOKENS * DIM)
                         : nullptr;

    enorm_kernel<<<NCODES / 8, 256>>>(e);
    vq_kernel<<<N_TOKENS / TM, 256>>>(z, e, out, out_idx);
}

// round 6
// speedup vs baseline: 1.4742x; 1.4742x over previous
#include <cuda_runtime.h>
#include <cuda_bf16.h>
#include <cstdint>
#include <float.h>

#define N_TOKENS 65536
#define DIM      256
#define NCODES   4096
#define BN       32
#define NITER    (NCODES / BN)       // 128
#define THETA    0.01f

// SMEM layout (bytes, dynamic)
#define SM_BEST   0                   // 128 ints
#define SM_A      1024
#define A_MAT     (128 * 528)         // 67584: 128 rows x 264 bf16 (8-col pad)
#define SM_B      (SM_A + 2 * A_MAT)  // 136192
#define B_MAT     (32 * 528)          // 16896
#define B_BUF     (2 * B_MAT)         // 33792 (hi+lo)
#define SM_EN     (SM_B + 2 * B_BUF)  // 203776
#define SMEM_TOTAL (SM_EN + NCODES * 4)  // 220160

// device scratch
__device__ __nv_bfloat16 g_z_hi[(size_t)N_TOKENS * DIM];
__device__ __nv_bfloat16 g_z_lo[(size_t)N_TOKENS * DIM];
__device__ __nv_bfloat16 g_e_hi[NCODES * DIM];
__device__ __nv_bfloat16 g_e_lo[NCODES * DIM];
__device__ float g_half_enorm[NCODES];
__device__ int   g_rescue_count;
__device__ int   g_rescue_list[N_TOKENS];

// ---------------- helpers ----------------
__device__ __forceinline__ uint32_t smem_u32(const void* p) {
    uint32_t a;
    asm("{ .reg .u64 t; cvta.to.shared.u64 t, %1; cvt.u32.u64 %0, t; }" : "=r"(a) : "l"(p));
    return a;
}
__device__ __forceinline__ void ldsm4(uint32_t* r, uint32_t addr) {
    asm volatile("ldmatrix.sync.aligned.m8n8.x4.shared.b16 {%0,%1,%2,%3}, [%4];"
                 : "=r"(r[0]), "=r"(r[1]), "=r"(r[2]), "=r"(r[3]) : "r"(addr));
}
__device__ __forceinline__ void mma_bf16(float* c, const uint32_t* a, uint32_t b0, uint32_t b1) {
    asm volatile("mma.sync.aligned.m16n8k16.row.col.f32.bf16.bf16.f32 "
                 "{%0,%1,%2,%3}, {%4,%5,%6,%7}, {%8,%9}, {%0,%1,%2,%3};"
                 : "+f"(c[0]), "+f"(c[1]), "+f"(c[2]), "+f"(c[3])
                 : "r"(a[0]), "r"(a[1]), "r"(a[2]), "r"(a[3]), "r"(b0), "r"(b1));
}
__device__ __forceinline__ void cp16(uint32_t dst, const void* src) {
    asm volatile("cp.async.cg.shared.global [%0], [%1], 16;" :: "r"(dst), "l"(src) : "memory");
}
#define CP_COMMIT() asm volatile("cp.async.commit_group;" ::: "memory")
#define CP_WAIT0()  asm volatile("cp.async.wait_group 0;" ::: "memory")

// ---------------------------------------------------------------------------
// split fp32 -> (hi, lo) bf16 for z and e; reset rescue counter
// ---------------------------------------------------------------------------
__global__ void split_kernel(const float* __restrict__ z, const float* __restrict__ e) {
    if (blockIdx.x == 0 && threadIdx.x == 0) g_rescue_count = 0;
    const size_t zn4 = (size_t)N_TOKENS * DIM / 4;
    const size_t tn4 = zn4 + (size_t)NCODES * DIM / 4;
    for (size_t i4 = (size_t)blockIdx.x * blockDim.x + threadIdx.x; i4 < tn4;
         i4 += (size_t)gridDim.x * blockDim.x) {
        bool isz = i4 < zn4;
        size_t j4 = isz ? i4 : (i4 - zn4);
        float4 v = isz ? ((const float4*)z)[j4] : ((const float4*)e)[j4];
        __nv_bfloat16* hi = isz ? g_z_hi : g_e_hi;
        __nv_bfloat16* lo = isz ? g_z_lo : g_e_lo;
        float x[4] = {v.x, v.y, v.z, v.w};
        __nv_bfloat162 h2[2], l2[2];
        #pragma unroll
        for (int k = 0; k < 4; k++) {
            __nv_bfloat16 h = __float2bfloat16(x[k]);
            __nv_bfloat16 l = __float2bfloat16(x[k] - __bfloat162float(h));
            ((__nv_bfloat16*)h2)[k] = h;
            ((__nv_bfloat16*)l2)[k] = l;
        }
        ((__nv_bfloat162*)hi)[j4 * 2 + 0] = h2[0];
        ((__nv_bfloat162*)hi)[j4 * 2 + 1] = h2[1];
        ((__nv_bfloat162*)lo)[j4 * 2 + 0] = l2[0];
        ((__nv_bfloat162*)lo)[j4 * 2 + 1] = l2[1];
    }
}

__global__ void enorm_kernel(const float* __restrict__ e) {
    int row = blockIdx.x * 8 + (threadIdx.x >> 5);
    int lane = threadIdx.x & 31;
    const float4* ep = (const float4*)(e + (size_t)row * DIM);
    float s = 0.f;
    #pragma unroll
    for (int j = lane; j < DIM / 4; j += 32) {
        float4 v = ep[j];
        s += v.x * v.x + v.y * v.y + v.z * v.z + v.w * v.w;
    }
    #pragma unroll
    for (int o = 16; o; o >>= 1) s += __shfl_xor_sync(0xffffffffu, s, o);
    if (lane == 0) g_half_enorm[row] = 0.5f * s;
}

// ---------------------------------------------------------------------------
// main HMMA kernel: 128 tokens/CTA, 128 iters of 32 codes, bf16 hi/lo split
// ---------------------------------------------------------------------------
__global__ __launch_bounds__(256, 1)
void vq_kernel(const float* __restrict__ e,
               float* __restrict__ out_q, float* __restrict__ out_idx)
{
    extern __shared__ __align__(1024) char smem[];
    const uint32_t sb = smem_u32(smem);
    const int tid  = threadIdx.x;
    const int wid  = tid >> 5;
    const int lane = tid & 31;
    const int m0   = blockIdx.x * 128;
    const int wr   = wid * 16;          // warp's row base

    // ---- resident A (z hi/lo), padded rows (528B stride) ----
    for (int idx = tid; idx < 8192; idx += 256) {
        int mat = idx >> 12, row = (idx >> 5) & 127, c16 = idx & 31;
        const __nv_bfloat16* src = (mat ? g_z_lo : g_z_hi) + (size_t)(m0 + row) * DIM + c16 * 8;
        *(uint4*)(smem + SM_A + mat * A_MAT + row * 528 + c16 * 16) = *(const uint4*)src;
    }
    // ---- enorm table into smem ----
    for (int i = tid; i < NCODES; i += 256)
        ((float*)(smem + SM_EN))[i] = g_half_enorm[i];

    // ---- prologue: B chunk 0 into buf 0 ----
    {
        for (int idx = tid; idx < 2048; idx += 256) {
            int mat = idx >> 10, row = (idx >> 5) & 31, c16 = idx & 31;
            const __nv_bfloat16* src = (mat ? g_e_lo : g_e_hi) + (size_t)row * DIM + c16 * 8;
            cp16(sb + SM_B + mat * B_MAT + row * 528 + c16 * 16, src);
        }
        CP_COMMIT();
    }
    CP_WAIT0();
    __syncthreads();

    // fragment base addresses
    const uint32_t Abase = sb + SM_A + (uint32_t)(wr + (lane & 15)) * 528 + (uint32_t)(lane >> 4) * 16;
    const uint32_t Blane = (uint32_t)lane * 528;
    const int tg = lane & 3;

    // per-row top-2 trackers (rows wr+(lane>>2) and +8)
    float b1a = -FLT_MAX, b2a = -FLT_MAX, b1b = -FLT_MAX, b2b = -FLT_MAX;
    int   bia = 0, bib = 0;

    int buf = 0;
    for (int c = 0; c < NITER; c++) {
        // issue loads for next chunk into other buffer
        if (c + 1 < NITER) {
            const int n0n = (c + 1) * BN;
            const uint32_t db = sb + SM_B + (buf ^ 1) * B_BUF;
            for (int idx = tid; idx < 2048; idx += 256) {
                int mat = idx >> 10, row = (idx >> 5) & 31, c16 = idx & 31;
                const __nv_bfloat16* src =
                    (mat ? g_e_lo : g_e_hi) + (size_t)(n0n + row) * DIM + c16 * 8;
                cp16(db + mat * B_MAT + row * 528 + c16 * 16, src);
            }
            CP_COMMIT();
        }

        // ---- compute 128x32 score tile ----
        float acc[4][4];
        #pragma unroll
        for (int n = 0; n < 4; n++)
            #pragma unroll
            for (int r = 0; r < 4; r++) acc[n][r] = 0.f;

        const uint32_t Bh = sb + SM_B + buf * B_BUF + Blane;
        const uint32_t Bl = Bh + B_MAT;

        #pragma unroll
        for (int ks = 0; ks < 16; ks++) {
            const uint32_t off = ks * 32;
            uint32_t ah[4], al[4], bh0[4], bh1[4], bl0[4], bl1[4];
            ldsm4(ah, Abase + off);
            ldsm4(al, Abase + A_MAT + off);
            ldsm4(bh0, Bh + off);
            ldsm4(bh1, Bh + off + 16);
            ldsm4(bl0, Bl + off);
            ldsm4(bl1, Bl + off + 16);
            #pragma unroll
            for (int n = 0; n < 4; n++) mma_bf16(acc[n], ah, bh0[n], bh1[n]);
            #pragma unroll
            for (int n = 0; n < 4; n++) mma_bf16(acc[n], ah, bl0[n], bl1[n]);
            #pragma unroll
            for (int n = 0; n < 4; n++) mma_bf16(acc[n], al, bh0[n], bh1[n]);
        }

        // ---- epilogue: running argmax (+top-2) per row ----
        const int n0 = c * BN;
        const float* en = (const float*)(smem + SM_EN) + n0;
        #pragma unroll
        for (int n = 0; n < 4; n++) {
            const int ce = n * 8 + tg * 2;
            const float e0 = en[ce], e1 = en[ce + 1];
            float s;
            s = acc[n][0] - e0;
            if (s > b1a) { b2a = b1a; b1a = s; bia = n0 + ce; } else if (s > b2a) b2a = s;
            s = acc[n][1] - e1;
            if (s > b1a) { b2a = b1a; b1a = s; bia = n0 + ce + 1; } else if (s > b2a) b2a = s;
            s = acc[n][2] - e0;
            if (s > b1b) { b2b = b1b; b1b = s; bib = n0 + ce; } else if (s > b2b) b2b = s;
            s = acc[n][3] - e1;
            if (s > b1b) { b2b = b1b; b1b = s; bib = n0 + ce + 1; } else if (s > b2b) b2b = s;
        }

        if (c + 1 < NITER) CP_WAIT0();
        __syncthreads();
        buf ^= 1;
    }

    // ---- reduce across the 4 threads of each quad (same rows) ----
    #pragma unroll
    for (int o = 1; o <= 2; o <<= 1) {
        float ov1 = __shfl_xor_sync(0xffffffffu, b1a, o);
        float ov2 = __shfl_xor_sync(0xffffffffu, b2a, o);
        int   oi  = __shfl_xor_sync(0xffffffffu, bia, o);
        if (ov1 > b1a || (ov1 == b1a && oi < bia)) { b2a = fmaxf(b1a, ov2); b1a = ov1; bia = oi; }
        else b2a = fmaxf(b2a, fmaxf(ov1 == b1a ? -FLT_MAX : ov1, ov2));
        if (ov1 == __shfl_xor_sync(0xffffffffu, b1a, 0)) {} // no-op keep regs
        ov1 = __shfl_xor_sync(0xffffffffu, b1b, o);
        ov2 = __shfl_xor_sync(0xffffffffu, b2b, o);
        oi  = __shfl_xor_sync(0xffffffffu, bib, o);
        if (ov1 > b1b || (ov1 == b1b && oi < bib)) { b2b = fmaxf(b1b, ov2); b1b = ov1; bib = oi; }
        else b2b = fmaxf(b2b, fmaxf(ov1 == b1b ? -FLT_MAX : ov1, ov2));
    }
    // note: for the tie case (ov1 == b1) the gap becomes 0 via b2 = fmax(b2, ov2)...
    // conservative: also force rescue on exact cross-thread tie
    {
        float t1 = __shfl_xor_sync(0xffffffffu, b1a, 1);
        (void)t1;
    }

    if (tg == 0) {
        const int r0 = wr + (lane >> 2), r1 = r0 + 8;
        ((int*)(smem + SM_BEST))[r0] = bia;
        ((int*)(smem + SM_BEST))[r1] = bib;
        if (out_idx) { out_idx[m0 + r0] = (float)bia; out_idx[m0 + r1] = (float)bib; }
        if (b1a - b2a < THETA) { int s = atomicAdd(&g_rescue_count, 1); g_rescue_list[s] = m0 + r0; }
        if (b1b - b2b < THETA) { int s = atomicAdd(&g_rescue_count, 1); g_rescue_list[s] = m0 + r1; }
    }
    __syncthreads();

    // ---- gather winning embedding rows (coalesced) ----
    const int* sbest = (const int*)(smem + SM_BEST);
    for (int i4 = tid; i4 < 128 * (DIM / 4); i4 += 256) {
        int r = i4 >> 6, cc = i4 & 63;
        int code = sbest[r];
        ((float4*)out_q)[(size_t)(m0 + r) * (DIM / 4) + cc] =
            ((const float4*)e)[(size_t)code * (DIM / 4) + cc];
    }
}

// ---------------------------------------------------------------------------
// exact fp32 rescue for flagged (near-tie) tokens
// ---------------------------------------------------------------------------
__global__ void rescue_kernel(const float* __restrict__ z, const float* __restrict__ e,
                              float* __restrict__ out_q, float* __restrict__ out_idx)
{
    __shared__ float sz[DIM];
    __shared__ float rv[256];
    __shared__ int   ri[256];
    const int cnt = g_rescue_count;
    for (int it = blockIdx.x; it < cnt; it += gridDim.x) {
        const int t = g_rescue_list[it];
        __syncthreads();
        sz[threadIdx.x] = z[(size_t)t * DIM + threadIdx.x];
        __syncthreads();
        float bv = -FLT_MAX;
        int bidx = 0x7fffffff;
        for (int code = threadIdx.x; code < NCODES; code += 256) {
            const float4* er = (const float4*)(e + (size_t)code * DIM);
            float s = 0.f;
            #pragma unroll
            for (int k = 0; k < DIM / 4; k++) {
                float4 v = __ldg(er + k);
                s += sz[4 * k] * v.x + sz[4 * k + 1] * v.y + sz[4 * k + 2] * v.z + sz[4 * k + 3] * v.w;
            }
            s -= g_half_enorm[code];
            if (s > bv) { bv = s; bidx = code; }
        }
        rv[threadIdx.x] = bv;
        ri[threadIdx.x] = bidx;
        __syncthreads();
        for (int off = 128; off; off >>= 1) {
            if (threadIdx.x < off) {
                float ov = rv[threadIdx.x + off];
                int oi = ri[threadIdx.x + off];
                if (ov > rv[threadIdx.x] || (ov == rv[threadIdx.x] && oi < ri[threadIdx.x])) {
                    rv[threadIdx.x] = ov;
                    ri[threadIdx.x] = oi;
                }
            }
            __syncthreads();
        }
        const int win = ri[0];
        if (threadIdx.x < 64)
            ((float4*)out_q)[(size_t)t * (DIM / 4) + threadIdx.x] =
                ((const float4*)e)[(size_t)win * (DIM / 4) + threadIdx.x];
        if (threadIdx.x == 0 && out_idx) out_idx[t] = (float)win;
    }
}

// ---------------------------------------------------------------------------
extern "C" void kernel_launch(void* const* d_in, const int* in_sizes, int n_in,
                              void* d_out, int out_size)
{
    const float* z = (const float*)d_in[0];
    const float* e = (const float*)d_in[1];
    if (n_in >= 2 && in_sizes[0] == NCODES * DIM && in_sizes[1] == N_TOKENS * DIM) {
        const float* t = z; z = e; e = t;
    }

    float* out = (float*)d_out;
    float* out_idx = (out_size >= N_TOKENS * DIM + N_TOKENS)
                         ? (out + (size_t)N_TOKENS * DIM)
                         : nullptr;

    cudaFuncSetAttribute(vq_kernel, cudaFuncAttributeMaxDynamicSharedMemorySize, SMEM_TOTAL);

    split_kernel<<<4096, 256>>>(z, e);
    enorm_kernel<<<NCODES / 8, 256>>>(e);
    vq_kernel<<<N_TOKENS / 128, 256, SMEM_TOTAL>>>(e, out, out_idx);
    rescue_kernel<<<128, 256>>>(z, e, out, out_idx);
}

// round 8
// speedup vs baseline: 3.4636x; 2.3495x over previous
#include <cuda_runtime.h>
#include <cuda_fp16.h>
#include <cstdint>
#include <float.h>

#define N_TOKENS 65536
#define DIM      256
#define NCODES   4096
#define BN       64
#define NITER    (NCODES / BN)       // 64
#define THETA    0.05f

// SMEM layout (bytes, dynamic)
#define SM_BEST   0                    // 128 ints
#define SM_A      1024
#define A_MAT     (128 * 528)          // 67584: 128 rows x (256+8) fp16
#define SM_B      (SM_A + A_MAT)       // 68608
#define B_TILE    (64 * 528)           // 33792 per buffer
#define SM_EN     (SM_B + 2 * B_TILE)  // 136192
#define SMEM_TOTAL (SM_EN + NCODES * 4)  // 152576

// device scratch
__device__ __half g_zh[(size_t)N_TOKENS * DIM];
__device__ __half g_eh[NCODES * DIM];
__device__ float  g_half_enorm[NCODES];
__device__ int    g_rescue_count;
__device__ int    g_rescue_list[N_TOKENS];

// ---------------- helpers ----------------
__device__ __forceinline__ uint32_t smem_u32(const void* p) {
    uint32_t a;
    asm("{ .reg .u64 t; cvta.to.shared.u64 t, %1; cvt.u32.u64 %0, t; }" : "=r"(a) : "l"(p));
    return a;
}
__device__ __forceinline__ void ldsm4(uint32_t* r, uint32_t addr) {
    asm volatile("ldmatrix.sync.aligned.m8n8.x4.shared.b16 {%0,%1,%2,%3}, [%4];"
                 : "=r"(r[0]), "=r"(r[1]), "=r"(r[2]), "=r"(r[3]) : "r"(addr));
}
__device__ __forceinline__ void mma_f16(float* c, const uint32_t* a, uint32_t b0, uint32_t b1) {
    asm volatile("mma.sync.aligned.m16n8k16.row.col.f32.f16.f16.f32 "
                 "{%0,%1,%2,%3}, {%4,%5,%6,%7}, {%8,%9}, {%0,%1,%2,%3};"
                 : "+f"(c[0]), "+f"(c[1]), "+f"(c[2]), "+f"(c[3])
                 : "r"(a[0]), "r"(a[1]), "r"(a[2]), "r"(a[3]), "r"(b0), "r"(b1));
}
__device__ __forceinline__ void cp16(uint32_t dst, const void* src) {
    asm volatile("cp.async.cg.shared.global [%0], [%1], 16;" :: "r"(dst), "l"(src) : "memory");
}
#define CP_COMMIT() asm volatile("cp.async.commit_group;" ::: "memory")
#define CP_WAIT0()  asm volatile("cp.async.wait_group 0;" ::: "memory")

// top-2 merge used in cross-lane reduction; exact cross-source tie => gap 0 (forces rescue)
__device__ __forceinline__ void merge2(float& b1, float& b2, int& bi,
                                       float ov1, float ov2, int oi) {
    if (ov1 > b1)       { b2 = fmaxf(b1, ov2); b1 = ov1; bi = oi; }
    else if (ov1 == b1) { b2 = b1; if (oi < bi) bi = oi; }
    else                { b2 = fmaxf(b2, ov1); }
}

// ---------------------------------------------------------------------------
// convert fp32 -> fp16 for z and e; reset rescue counter
// ---------------------------------------------------------------------------
__global__ void convert_kernel(const float* __restrict__ z, const float* __restrict__ e) {
    if (blockIdx.x == 0 && threadIdx.x == 0) g_rescue_count = 0;
    const size_t zn4 = (size_t)N_TOKENS * DIM / 4;
    const size_t tn4 = zn4 + (size_t)NCODES * DIM / 4;
    for (size_t i4 = (size_t)blockIdx.x * blockDim.x + threadIdx.x; i4 < tn4;
         i4 += (size_t)gridDim.x * blockDim.x) {
        bool isz = i4 < zn4;
        size_t j4 = isz ? i4 : (i4 - zn4);
        float4 v = isz ? ((const float4*)z)[j4] : ((const float4*)e)[j4];
        __half2* dst = (__half2*)(isz ? g_zh : g_eh);
        dst[j4 * 2 + 0] = __floats2half2_rn(v.x, v.y);
        dst[j4 * 2 + 1] = __floats2half2_rn(v.z, v.w);
    }
}

__global__ void enorm_kernel(const float* __restrict__ e) {
    int row = blockIdx.x * 8 + (threadIdx.x >> 5);
    int lane = threadIdx.x & 31;
    const float4* ep = (const float4*)(e + (size_t)row * DIM);
    float s = 0.f;
    #pragma unroll
    for (int j = lane; j < DIM / 4; j += 32) {
        float4 v = ep[j];
        s += v.x * v.x + v.y * v.y + v.z * v.z + v.w * v.w;
    }
    #pragma unroll
    for (int o = 16; o; o >>= 1) s += __shfl_xor_sync(0xffffffffu, s, o);
    if (lane == 0) g_half_enorm[row] = 0.5f * s;
}

// ---------------------------------------------------------------------------
// main HMMA kernel: 128 tokens/CTA, 64 iters of 64 codes, single fp16 GEMM
// ---------------------------------------------------------------------------
__global__ __launch_bounds__(256, 1)
void vq_kernel(const float* __restrict__ e,
               float* __restrict__ out_q, float* __restrict__ out_idx)
{
    extern __shared__ __align__(1024) char smem[];
    const uint32_t sb = smem_u32(smem);
    const int tid  = threadIdx.x;
    const int wid  = tid >> 5;
    const int lane = tid & 31;
    const int m0   = blockIdx.x * 128;
    const int wr   = wid * 16;

    // resident A (z fp16), 528B row stride
    for (int idx = tid; idx < 4096; idx += 256) {
        int row = idx >> 5, c16 = idx & 31;
        const __half* src = g_zh + (size_t)(m0 + row) * DIM + c16 * 8;
        *(uint4*)(smem + SM_A + row * 528 + c16 * 16) = *(const uint4*)src;
    }
    for (int i = tid; i < NCODES; i += 256)
        ((float*)(smem + SM_EN))[i] = g_half_enorm[i];

    // prologue: B chunk 0 -> buf 0
    for (int idx = tid; idx < 2048; idx += 256) {
        int row = idx >> 5, c16 = idx & 31;
        cp16(sb + SM_B + row * 528 + c16 * 16, g_eh + (size_t)row * DIM + c16 * 8);
    }
    CP_COMMIT();
    CP_WAIT0();
    __syncthreads();

    const uint32_t Abase = sb + SM_A + (uint32_t)(wr + (lane & 15)) * 528
                         + (uint32_t)(lane >> 4) * 16;
    const uint32_t Blane = (uint32_t)lane * 528;
    const int tg = lane & 3;

    float b1a = -FLT_MAX, b2a = -FLT_MAX, b1b = -FLT_MAX, b2b = -FLT_MAX;
    int   bia = 0, bib = 0;

    int buf = 0;
    for (int c = 0; c < NITER; c++) {
        if (c + 1 < NITER) {
            const int n0n = (c + 1) * BN;
            const uint32_t db = sb + SM_B + (buf ^ 1) * B_TILE;
            for (int idx = tid; idx < 2048; idx += 256) {
                int row = idx >> 5, c16 = idx & 31;
                cp16(db + row * 528 + c16 * 16, g_eh + (size_t)(n0n + row) * DIM + c16 * 8);
            }
            CP_COMMIT();
        }

        float acc[8][4];
        #pragma unroll
        for (int n = 0; n < 8; n++)
            #pragma unroll
            for (int r = 0; r < 4; r++) acc[n][r] = 0.f;

        const uint32_t B0 = sb + SM_B + buf * B_TILE + Blane;   // codes 0..31
        const uint32_t B1 = B0 + 32 * 528;                      // codes 32..63

        #pragma unroll
        for (int ks = 0; ks < 16; ks++) {
            const uint32_t off = ks * 32;
            uint32_t a[4], p0[4], p1[4], q0[4], q1[4];
            ldsm4(a, Abase + off);
            ldsm4(p0, B0 + off);
            ldsm4(p1, B0 + off + 16);
            ldsm4(q0, B1 + off);
            ldsm4(q1, B1 + off + 16);
            #pragma unroll
            for (int n = 0; n < 4; n++) mma_f16(acc[n], a, p0[n], p1[n]);
            #pragma unroll
            for (int n = 0; n < 4; n++) mma_f16(acc[4 + n], a, q0[n], q1[n]);
        }

        // epilogue: top-2 per row
        const int n0 = c * BN;
        const float* en = (const float*)(smem + SM_EN) + n0;
        #pragma unroll
        for (int n = 0; n < 8; n++) {
            const int ce = (n & 3) * 8 + (n >> 2) * 32 + tg * 2;
            const float e0 = en[ce], e1 = en[ce + 1];
            float s;
            s = acc[n][0] - e0;
            if (s > b1a) { b2a = b1a; b1a = s; bia = n0 + ce; } else if (s > b2a) b2a = s;
            s = acc[n][1] - e1;
            if (s > b1a) { b2a = b1a; b1a = s; bia = n0 + ce + 1; } else if (s > b2a) b2a = s;
            s = acc[n][2] - e0;
            if (s > b1b) { b2b = b1b; b1b = s; bib = n0 + ce; } else if (s > b2b) b2b = s;
            s = acc[n][3] - e1;
            if (s > b1b) { b2b = b1b; b1b = s; bib = n0 + ce + 1; } else if (s > b2b) b2b = s;
        }

        if (c + 1 < NITER) CP_WAIT0();
        __syncthreads();
        buf ^= 1;
    }

    // reduce across quad (4 threads share rows)
    #pragma unroll
    for (int o = 1; o <= 2; o <<= 1) {
        float ov1 = __shfl_xor_sync(0xffffffffu, b1a, o);
        float ov2 = __shfl_xor_sync(0xffffffffu, b2a, o);
        int   oi  = __shfl_xor_sync(0xffffffffu, bia, o);
        merge2(b1a, b2a, bia, ov1, ov2, oi);
        ov1 = __shfl_xor_sync(0xffffffffu, b1b, o);
        ov2 = __shfl_xor_sync(0xffffffffu, b2b, o);
        oi  = __shfl_xor_sync(0xffffffffu, bib, o);
        merge2(b1b, b2b, bib, ov1, ov2, oi);
    }

    if (tg == 0) {
        const int r0 = wr + (lane >> 2), r1 = r0 + 8;
        ((int*)(smem + SM_BEST))[r0] = bia;
        ((int*)(smem + SM_BEST))[r1] = bib;
        if (out_idx) { out_idx[m0 + r0] = (float)bia; out_idx[m0 + r1] = (float)bib; }
        if (b1a - b2a < THETA) { int s = atomicAdd(&g_rescue_count, 1); g_rescue_list[s] = m0 + r0; }
        if (b1b - b2b < THETA) { int s = atomicAdd(&g_rescue_count, 1); g_rescue_list[s] = m0 + r1; }
    }
    __syncthreads();

    // gather winning embedding rows (fp32, coalesced)
    const int* sbest = (const int*)(smem + SM_BEST);
    for (int i4 = tid; i4 < 128 * (DIM / 4); i4 += 256) {
        int r = i4 >> 6, cc = i4 & 63;
        int code = sbest[r];
        ((float4*)out_q)[(size_t)(m0 + r) * (DIM / 4) + cc] =
            ((const float4*)e)[(size_t)code * (DIM / 4) + cc];
    }
}

// ---------------------------------------------------------------------------
// batched exact fp32 rescue: 8 tokens per block share one scan of e
// ---------------------------------------------------------------------------
__global__ void rescue_kernel(const float* __restrict__ z, const float* __restrict__ e,
                              float* __restrict__ out_q, float* __restrict__ out_idx)
{
    __shared__ float sz[8][260];
    __shared__ float rv[256];
    __shared__ int   ri[256];
    __shared__ int   s_win;
    const int tid = threadIdx.x;
    const int cnt = g_rescue_count;

    for (int g = blockIdx.x; g * 8 < cnt; g += gridDim.x) {
        const int nt = min(8, cnt - g * 8);
        __syncthreads();
        for (int i = tid; i < nt * DIM; i += 256) {
            int t = i >> 8, k = i & 255;
            sz[t][k] = z[(size_t)g_rescue_list[g * 8 + t] * DIM + k];
        }
        __syncthreads();

        float bv[8];
        int   bx[8];
        #pragma unroll
        for (int t = 0; t < 8; t++) { bv[t] = -FLT_MAX; bx[t] = 0x7fffffff; }

        for (int code = tid; code < NCODES; code += 256) {
            const float4* er = (const float4*)(e + (size_t)code * DIM);
            float acc[8];
            #pragma unroll
            for (int t = 0; t < 8; t++) acc[t] = 0.f;
            #pragma unroll 4
            for (int k4 = 0; k4 < DIM / 4; k4++) {
                float4 v = __ldg(er + k4);
                #pragma unroll
                for (int t = 0; t < 8; t++) {
                    acc[t] += sz[t][4 * k4] * v.x + sz[t][4 * k4 + 1] * v.y
                            + sz[t][4 * k4 + 2] * v.z + sz[t][4 * k4 + 3] * v.w;
                }
            }
            const float he = g_half_enorm[code];
            #pragma unroll
            for (int t = 0; t < 8; t++) {
                float s = acc[t] - he;
                if (s > bv[t]) { bv[t] = s; bx[t] = code; }   // ascending codes: first wins
            }
        }

        for (int t = 0; t < nt; t++) {
            rv[tid] = bv[t];
            ri[tid] = bx[t];
            __syncthreads();
            for (int off = 128; off; off >>= 1) {
                if (tid < off) {
                    float ov = rv[tid + off];
                    int oi = ri[tid + off];
                    if (ov > rv[tid] || (ov == rv[tid] && oi < ri[tid])) {
                        rv[tid] = ov;
                        ri[tid] = oi;
                    }
                }
                __syncthreads();
            }
            if (tid == 0) s_win = ri[0];
            __syncthreads();
            const int win = s_win;
            const int tok = g_rescue_list[g * 8 + t];
            if (tid < 64)
                ((float4*)out_q)[(size_t)tok * (DIM / 4) + tid] =
                    ((const float4*)e)[(size_t)win * (DIM / 4) + tid];
            if (tid == 0 && out_idx) out_idx[tok] = (float)win;
            __syncthreads();
        }
    }
}

// ---------------------------------------------------------------------------
extern "C" void kernel_launch(void* const* d_in, const int* in_sizes, int n_in,
                              void* d_out, int out_size)
{
    const float* z = (const float*)d_in[0];
    const float* e = (const float*)d_in[1];
    if (n_in >= 2 && in_sizes[0] == NCODES * DIM && in_sizes[1] == N_TOKENS * DIM) {
        const float* t = z; z = e; e = t;
    }

    float* out = (float*)d_out;
    float* out_idx = (out_size >= N_TOKENS * DIM + N_TOKENS)
                         ? (out + (size_t)N_TOKENS * DIM)
                         : nullptr;

    cudaFuncSetAttribute(vq_kernel, cudaFuncAttributeMaxDynamicSharedMemorySize, SMEM_TOTAL);

    convert_kernel<<<2048, 256>>>(z, e);
    enorm_kernel<<<NCODES / 8, 256>>>(e);
    vq_kernel<<<N_TOKENS / 128, 256, SMEM_TOTAL>>>(e, out, out_idx);
    rescue_kernel<<<512, 256>>>(z, e, out, out_idx);
}

// round 13
// speedup vs baseline: 3.8398x; 1.1086x over previous
#include <cuda_runtime.h>
#include <cuda_fp16.h>
#include <cstdint>
#include <float.h>

#define N_TOKENS 65536
#define DIM      256
#define NCODES   4096
#define BN       64
#define NITER    (NCODES / BN)       // 64
#define THETA    0.05f
#define NSLICE   8                   // rescue code slices (512 codes each)

// SMEM layout (bytes, dynamic)
#define SM_BEST   0                    // 128 ints
#define SM_A      1024
#define A_MAT     (128 * 528)          // 67584: 128 rows x (256+8) fp16
#define SM_B      (SM_A + A_MAT)       // 68608
#define B_TILE    (64 * 528)           // 33792 per buffer
#define SM_EN     (SM_B + 2 * B_TILE)  // 136192
#define SMEM_TOTAL (SM_EN + NCODES * 4)  // 152576

// device scratch
__device__ __half g_eh[NCODES * DIM];
__device__ float  g_half_enorm[NCODES];
__device__ int    g_rescue_count;
__device__ int    g_rescue_list[N_TOKENS];
__device__ unsigned long long g_best[N_TOKENS];   // packed (score||4095-code) per slot

// ---------------- helpers ----------------
__device__ __forceinline__ uint32_t smem_u32(const void* p) {
    uint32_t a;
    asm("{ .reg .u64 t; cvta.to.shared.u64 t, %1; cvt.u32.u64 %0, t; }" : "=r"(a) : "l"(p));
    return a;
}
__device__ __forceinline__ uint32_t h2_as_u32(__half2 h) {
    union { __half2 h; uint32_t u; } c;
    c.h = h;
    return c.u;
}
__device__ __forceinline__ void ldsm4(uint32_t* r, uint32_t addr) {
    asm volatile("ldmatrix.sync.aligned.m8n8.x4.shared.b16 {%0,%1,%2,%3}, [%4];"
                 : "=r"(r[0]), "=r"(r[1]), "=r"(r[2]), "=r"(r[3]) : "r"(addr));
}
__device__ __forceinline__ void mma_f16(float* c, const uint32_t* a, uint32_t b0, uint32_t b1) {
    asm volatile("mma.sync.aligned.m16n8k16.row.col.f32.f16.f16.f32 "
                 "{%0,%1,%2,%3}, {%4,%5,%6,%7}, {%8,%9}, {%0,%1,%2,%3};"
                 : "+f"(c[0]), "+f"(c[1]), "+f"(c[2]), "+f"(c[3])
                 : "r"(a[0]), "r"(a[1]), "r"(a[2]), "r"(a[3]), "r"(b0), "r"(b1));
}
__device__ __forceinline__ void cp16(uint32_t dst, const void* src) {
    asm volatile("cp.async.cg.shared.global [%0], [%1], 16;" :: "r"(dst), "l"(src) : "memory");
}
#define CP_COMMIT() asm volatile("cp.async.commit_group;" ::: "memory")
#define CP_WAIT0()  asm volatile("cp.async.wait_group 0;" ::: "memory")

__device__ __forceinline__ void merge2(float& b1, float& b2, int& bi,
                                       float ov1, float ov2, int oi) {
    if (ov1 > b1)       { b2 = fmaxf(b1, ov2); b1 = ov1; bi = oi; }
    else if (ov1 == b1) { b2 = b1; if (oi < bi) bi = oi; }
    else                { b2 = fmaxf(b2, ov1); }
}

// order-preserving float -> uint32
__device__ __forceinline__ uint32_t f2u_ord(float f) {
    uint32_t u = __float_as_uint(f);
    return (int)u >= 0 ? (u | 0x80000000u) : ~u;
}

// ---------------------------------------------------------------------------
// convert fp32 -> fp16 for e only; reset rescue counter
// ---------------------------------------------------------------------------
__global__ void convert_kernel(const float* __restrict__ e) {
    if (blockIdx.x == 0 && threadIdx.x == 0) g_rescue_count = 0;
    const int n4 = NCODES * DIM / 4;
    for (int i4 = blockIdx.x * blockDim.x + threadIdx.x; i4 < n4;
         i4 += gridDim.x * blockDim.x) {
        float4 v = ((const float4*)e)[i4];
        ((__half2*)g_eh)[i4 * 2 + 0] = __floats2half2_rn(v.x, v.y);
        ((__half2*)g_eh)[i4 * 2 + 1] = __floats2half2_rn(v.z, v.w);
    }
}

__global__ void enorm_kernel(const float* __restrict__ e) {
    int row = blockIdx.x * 8 + (threadIdx.x >> 5);
    int lane = threadIdx.x & 31;
    const float4* ep = (const float4*)(e + (size_t)row * DIM);
    float s = 0.f;
    #pragma unroll
    for (int j = lane; j < DIM / 4; j += 32) {
        float4 v = ep[j];
        s += v.x * v.x + v.y * v.y + v.z * v.z + v.w * v.w;
    }
    #pragma unroll
    for (int o = 16; o; o >>= 1) s += __shfl_xor_sync(0xffffffffu, s, o);
    if (lane == 0) g_half_enorm[row] = 0.5f * s;
}

// ---------------------------------------------------------------------------
// main HMMA kernel: 128 tokens/CTA, 64 iters of 64 codes, fp16 GEMM,
// fused z fp32->fp16 conversion
// ---------------------------------------------------------------------------
__global__ __launch_bounds__(256, 1)
void vq_kernel(const float* __restrict__ z, const float* __restrict__ e,
               float* __restrict__ out_q, float* __restrict__ out_idx)
{
    extern __shared__ __align__(1024) char smem[];
    const uint32_t sb = smem_u32(smem);
    const int tid  = threadIdx.x;
    const int wid  = tid >> 5;
    const int lane = tid & 31;
    const int m0   = blockIdx.x * 128;
    const int wr   = wid * 16;

    // resident A: read z fp32, convert to fp16 in smem (528B row stride)
    for (int idx = tid; idx < 8192; idx += 256) {
        int row = idx >> 6, c4 = idx & 63;
        float4 v = *(const float4*)(z + (size_t)(m0 + row) * DIM + c4 * 4);
        uint2 h;
        h.x = h2_as_u32(__floats2half2_rn(v.x, v.y));
        h.y = h2_as_u32(__floats2half2_rn(v.z, v.w));
        *(uint2*)(smem + SM_A + row * 528 + c4 * 8) = h;
    }
    for (int i = tid; i < NCODES; i += 256)
        ((float*)(smem + SM_EN))[i] = g_half_enorm[i];

    // prologue: B chunk 0 -> buf 0
    for (int idx = tid; idx < 2048; idx += 256) {
        int row = idx >> 5, c16 = idx & 31;
        cp16(sb + SM_B + row * 528 + c16 * 16, g_eh + (size_t)row * DIM + c16 * 8);
    }
    CP_COMMIT();
    CP_WAIT0();
    __syncthreads();

    const uint32_t Abase = sb + SM_A + (uint32_t)(wr + (lane & 15)) * 528
                         + (uint32_t)(lane >> 4) * 16;
    const uint32_t Blane = (uint32_t)lane * 528;
    const int tg = lane & 3;

    float b1a = -FLT_MAX, b2a = -FLT_MAX, b1b = -FLT_MAX, b2b = -FLT_MAX;
    int   bia = 0, bib = 0;

    int buf = 0;
    for (int c = 0; c < NITER; c++) {
        if (c + 1 < NITER) {
            const int n0n = (c + 1) * BN;
            const uint32_t db = sb + SM_B + (buf ^ 1) * B_TILE;
            for (int idx = tid; idx < 2048; idx += 256) {
                int row = idx >> 5, c16 = idx & 31;
                cp16(db + row * 528 + c16 * 16, g_eh + (size_t)(n0n + row) * DIM + c16 * 8);
            }
            CP_COMMIT();
        }

        float acc[8][4];
        #pragma unroll
        for (int n = 0; n < 8; n++)
            #pragma unroll
            for (int r = 0; r < 4; r++) acc[n][r] = 0.f;

        const uint32_t B0 = sb + SM_B + buf * B_TILE + Blane;
        const uint32_t B1 = B0 + 32 * 528;

        #pragma unroll
        for (int ks = 0; ks < 16; ks++) {
            const uint32_t off = ks * 32;
            uint32_t a[4], p0[4], p1[4], q0[4], q1[4];
            ldsm4(a, Abase + off);
            ldsm4(p0, B0 + off);
            ldsm4(p1, B0 + off + 16);
            ldsm4(q0, B1 + off);
            ldsm4(q1, B1 + off + 16);
            #pragma unroll
            for (int n = 0; n < 4; n++) mma_f16(acc[n], a, p0[n], p1[n]);
            #pragma unroll
            for (int n = 0; n < 4; n++) mma_f16(acc[4 + n], a, q0[n], q1[n]);
        }

        const int n0 = c * BN;
        const float* en = (const float*)(smem + SM_EN) + n0;
        #pragma unroll
        for (int n = 0; n < 8; n++) {
            const int ce = (n & 3) * 8 + (n >> 2) * 32 + tg * 2;
            const float e0 = en[ce], e1 = en[ce + 1];
            float s;
            s = acc[n][0] - e0;
            if (s > b1a) { b2a = b1a; b1a = s; bia = n0 + ce; } else if (s > b2a) b2a = s;
            s = acc[n][1] - e1;
            if (s > b1a) { b2a = b1a; b1a = s; bia = n0 + ce + 1; } else if (s > b2a) b2a = s;
            s = acc[n][2] - e0;
            if (s > b1b) { b2b = b1b; b1b = s; bib = n0 + ce; } else if (s > b2b) b2b = s;
            s = acc[n][3] - e1;
            if (s > b1b) { b2b = b1b; b1b = s; bib = n0 + ce + 1; } else if (s > b2b) b2b = s;
        }

        if (c + 1 < NITER) CP_WAIT0();
        __syncthreads();
        buf ^= 1;
    }

    // reduce across quad (4 threads share rows)
    #pragma unroll
    for (int o = 1; o <= 2; o <<= 1) {
        float ov1 = __shfl_xor_sync(0xffffffffu, b1a, o);
        float ov2 = __shfl_xor_sync(0xffffffffu, b2a, o);
        int   oi  = __shfl_xor_sync(0xffffffffu, bia, o);
        merge2(b1a, b2a, bia, ov1, ov2, oi);
        ov1 = __shfl_xor_sync(0xffffffffu, b1b, o);
        ov2 = __shfl_xor_sync(0xffffffffu, b2b, o);
        oi  = __shfl_xor_sync(0xffffffffu, bib, o);
        merge2(b1b, b2b, bib, ov1, ov2, oi);
    }

    if (tg == 0) {
        const int r0 = wr + (lane >> 2), r1 = r0 + 8;
        ((int*)(smem + SM_BEST))[r0] = bia;
        ((int*)(smem + SM_BEST))[r1] = bib;
        if (out_idx) { out_idx[m0 + r0] = (float)bia; out_idx[m0 + r1] = (float)bib; }
        if (b1a - b2a < THETA) {
            int s = atomicAdd(&g_rescue_count, 1);
            g_rescue_list[s] = m0 + r0;
            g_best[s] = 0ULL;
        }
        if (b1b - b2b < THETA) {
            int s = atomicAdd(&g_rescue_count, 1);
            g_rescue_list[s] = m0 + r1;
            g_best[s] = 0ULL;
        }
    }
    __syncthreads();

    // gather winning embedding rows (fp32, coalesced)
    const int* sbest = (const int*)(smem + SM_BEST);
    for (int i4 = tid; i4 < 128 * (DIM / 4); i4 += 256) {
        int r = i4 >> 6, cc = i4 & 63;
        int code = sbest[r];
        ((float4*)out_q)[(size_t)(m0 + r) * (DIM / 4) + cc] =
            ((const float4*)e)[(size_t)code * (DIM / 4) + cc];
    }
}

// ---------------------------------------------------------------------------
// 2-D exact fp32 rescue: block = (token-group of 8) x (code slice of 512)
// block-reduces to one candidate per token, publishes via packed atomicMax
// ---------------------------------------------------------------------------
__global__ void rescue_kernel(const float* __restrict__ z, const float* __restrict__ e)
{
    __shared__ float sz[8][260];
    __shared__ unsigned long long wb[8][8];   // [warp][token]
    const int tid = threadIdx.x;
    const int wid = tid >> 5;
    const int lane = tid & 31;
    const int cnt = g_rescue_count;
    const int ngroups = (cnt + 7) >> 3;

    for (int p = blockIdx.x; p < ngroups * NSLICE; p += gridDim.x) {
        const int grp = p / NSLICE;
        const int slice = p - grp * NSLICE;
        const int base = grp * 8;
        const int nt = min(8, cnt - base);
        __syncthreads();
        for (int i = tid; i < nt * DIM; i += 256) {
            int t = i >> 8, k = i & 255;
            sz[t][k] = z[(size_t)g_rescue_list[base + t] * DIM + k];
        }
        __syncthreads();

        unsigned long long bk[8];
        #pragma unroll
        for (int t = 0; t < 8; t++) bk[t] = 0ULL;

        const int c0 = slice * (NCODES / NSLICE);
        #pragma unroll
        for (int cc = 0; cc < 2; cc++) {
            const int code = c0 + cc * 256 + tid;
            const float4* er = (const float4*)(e + (size_t)code * DIM);
            float acc[8];
            #pragma unroll
            for (int t = 0; t < 8; t++) acc[t] = 0.f;
            #pragma unroll 4
            for (int k4 = 0; k4 < DIM / 4; k4++) {
                float4 v = __ldg(er + k4);
                #pragma unroll
                for (int t = 0; t < 8; t++) {
                    acc[t] += sz[t][4 * k4] * v.x + sz[t][4 * k4 + 1] * v.y
                            + sz[t][4 * k4 + 2] * v.z + sz[t][4 * k4 + 3] * v.w;
                }
            }
            const float he = g_half_enorm[code];
            #pragma unroll
            for (int t = 0; t < 8; t++) {
                float s = acc[t] - he;
                unsigned long long key =
                    ((unsigned long long)f2u_ord(s) << 32) | (uint32_t)(4095 - code);
                if (key > bk[t]) bk[t] = key;
            }
        }

        // warp reduce
        #pragma unroll
        for (int o = 16; o; o >>= 1) {
            #pragma unroll
            for (int t = 0; t < 8; t++) {
                unsigned long long ok = __shfl_xor_sync(0xffffffffu, bk[t], o);
                if (ok > bk[t]) bk[t] = ok;
            }
        }
        if (lane == 0) {
            #pragma unroll
            for (int t = 0; t < 8; t++) wb[wid][t] = bk[t];
        }
        __syncthreads();
        if (tid < 8 && tid < nt) {
            unsigned long long m = wb[0][tid];
            #pragma unroll
            for (int w = 1; w < 8; w++) if (wb[w][tid] > m) m = wb[w][tid];
            atomicMax(&g_best[base + tid], m);
        }
    }
}

// ---------------------------------------------------------------------------
// fixup: decode winners, write indices, gather rows. 64 threads/block.
// ---------------------------------------------------------------------------
__global__ void fixup_kernel(const float* __restrict__ e,
                             float* __restrict__ out_q, float* __restrict__ out_idx)
{
    const int cnt = g_rescue_count;
    for (int s = blockIdx.x; s < cnt; s += gridDim.x) {
        const int tok = g_rescue_list[s];
        const int code = 4095 - (int)(uint32_t)(g_best[s] & 0xFFFFFFFFULL);
        if (threadIdx.x == 0 && out_idx) out_idx[tok] = (float)code;
        ((float4*)out_q)[(size_t)tok * (DIM / 4) + threadIdx.x] =
            ((const float4*)e)[(size_t)code * (DIM / 4) + threadIdx.x];
    }
}

// ---------------------------------------------------------------------------
extern "C" void kernel_launch(void* const* d_in, const int* in_sizes, int n_in,
                              void* d_out, int out_size)
{
    const float* z = (const float*)d_in[0];
    const float* e = (const float*)d_in[1];
    if (n_in >= 2 && in_sizes[0] == NCODES * DIM && in_sizes[1] == N_TOKENS * DIM) {
        const float* t = z; z = e; e = t;
    }

    float* out = (float*)d_out;
    float* out_idx = (out_size >= N_TOKENS * DIM + N_TOKENS)
                         ? (out + (size_t)N_TOKENS * DIM)
                         : nullptr;

    cudaFuncSetAttribute(vq_kernel, cudaFuncAttributeMaxDynamicSharedMemorySize, SMEM_TOTAL);

    convert_kernel<<<256, 256>>>(e);
    enorm_kernel<<<NCODES / 8, 256>>>(e);
    vq_kernel<<<N_TOKENS / 128, 256, SMEM_TOTAL>>>(z, e, out, out_idx);
    rescue_kernel<<<1024, 256>>>(z, e);
    fixup_kernel<<<512, 64>>>(e, out, out_idx);
}

// round 16
// speedup vs baseline: 5.3474x; 1.3926x over previous
#include <cuda_runtime.h>
#include <cuda_fp16.h>
#include <cstdint>
#include <float.h>

#define N_TOKENS 65536
#define DIM      256
#define NCODES   4096
#define BN       32
#define NITER    (NCODES / BN)       // 128
#define THETA    0.05f
#define NSLICE   16                  // rescue code slices (256 codes each)

// SMEM layout (bytes, dynamic)  -- total ~100 KB => 2 CTAs/SM
#define SM_BEST   0                    // 128 ints (512 B)
#define SM_EN     512                  // 2 x 32 floats (256 B, double-buffered)
#define SM_A      1024
#define A_MAT     (128 * 528)          // 67584: 128 rows x (256+8) fp16
#define SM_B      (SM_A + A_MAT)       // 68608
#define B_TILE    (32 * 528)           // 16896 per buffer
#define SMEM_TOTAL (SM_B + 2 * B_TILE) // 102400

// device scratch
__device__ __align__(16) __half g_eh[NCODES * DIM];
__device__ __align__(16) float  g_half_enorm[NCODES];
__device__ int    g_rescue_count;
__device__ int    g_rescue_list[N_TOKENS];
__device__ unsigned long long g_best[N_TOKENS];   // packed (score||4095-code)

// ---------------- helpers ----------------
__device__ __forceinline__ uint32_t smem_u32(const void* p) {
    uint32_t a;
    asm("{ .reg .u64 t; cvta.to.shared.u64 t, %1; cvt.u32.u64 %0, t; }" : "=r"(a) : "l"(p));
    return a;
}
__device__ __forceinline__ uint32_t h2_as_u32(__half2 h) {
    union { __half2 h; uint32_t u; } c;
    c.h = h;
    return c.u;
}
__device__ __forceinline__ void ldsm4(uint32_t* r, uint32_t addr) {
    asm volatile("ldmatrix.sync.aligned.m8n8.x4.shared.b16 {%0,%1,%2,%3}, [%4];"
                 : "=r"(r[0]), "=r"(r[1]), "=r"(r[2]), "=r"(r[3]) : "r"(addr));
}
__device__ __forceinline__ void mma_f16(float* c, const uint32_t* a, uint32_t b0, uint32_t b1) {
    asm volatile("mma.sync.aligned.m16n8k16.row.col.f32.f16.f16.f32 "
                 "{%0,%1,%2,%3}, {%4,%5,%6,%7}, {%8,%9}, {%0,%1,%2,%3};"
                 : "+f"(c[0]), "+f"(c[1]), "+f"(c[2]), "+f"(c[3])
                 : "r"(a[0]), "r"(a[1]), "r"(a[2]), "r"(a[3]), "r"(b0), "r"(b1));
}
__device__ __forceinline__ void cp16(uint32_t dst, const void* src) {
    asm volatile("cp.async.cg.shared.global [%0], [%1], 16;" :: "r"(dst), "l"(src) : "memory");
}
#define CP_COMMIT() asm volatile("cp.async.commit_group;" ::: "memory")
#define CP_WAIT0()  asm volatile("cp.async.wait_group 0;" ::: "memory")

__device__ __forceinline__ void merge2(float& b1, float& b2, int& bi,
                                       float ov1, float ov2, int oi) {
    if (ov1 > b1)       { b2 = fmaxf(b1, ov2); b1 = ov1; bi = oi; }
    else if (ov1 == b1) { b2 = b1; if (oi < bi) bi = oi; }
    else                { b2 = fmaxf(b2, ov1); }
}

// order-preserving float -> uint32
__device__ __forceinline__ uint32_t f2u_ord(float f) {
    uint32_t u = __float_as_uint(f);
    return (int)u >= 0 ? (u | 0x80000000u) : ~u;
}

// ---------------------------------------------------------------------------
// convert fp32 -> fp16 for e only; reset rescue counter
// ---------------------------------------------------------------------------
__global__ void convert_kernel(const float* __restrict__ e) {
    if (blockIdx.x == 0 && threadIdx.x == 0) g_rescue_count = 0;
    const int n4 = NCODES * DIM / 4;
    for (int i4 = blockIdx.x * blockDim.x + threadIdx.x; i4 < n4;
         i4 += gridDim.x * blockDim.x) {
        float4 v = ((const float4*)e)[i4];
        ((__half2*)g_eh)[i4 * 2 + 0] = __floats2half2_rn(v.x, v.y);
        ((__half2*)g_eh)[i4 * 2 + 1] = __floats2half2_rn(v.z, v.w);
    }
}

__global__ void enorm_kernel(const float* __restrict__ e) {
    int row = blockIdx.x * 8 + (threadIdx.x >> 5);
    int lane = threadIdx.x & 31;
    const float4* ep = (const float4*)(e + (size_t)row * DIM);
    float s = 0.f;
    #pragma unroll
    for (int j = lane; j < DIM / 4; j += 32) {
        float4 v = ep[j];
        s += v.x * v.x + v.y * v.y + v.z * v.z + v.w * v.w;
    }
    #pragma unroll
    for (int o = 16; o; o >>= 1) s += __shfl_xor_sync(0xffffffffu, s, o);
    if (lane == 0) g_half_enorm[row] = 0.5f * s;
}

// ---------------------------------------------------------------------------
// main HMMA kernel: 128 tokens/CTA, 128 iters of 32 codes, 2 CTAs/SM
// ---------------------------------------------------------------------------
__global__ __launch_bounds__(256, 2)
void vq_kernel(const float* __restrict__ z, const float* __restrict__ e,
               float* __restrict__ out_q, float* __restrict__ out_idx)
{
    extern __shared__ __align__(1024) char smem[];
    const uint32_t sb = smem_u32(smem);
    const int tid  = threadIdx.x;
    const int wid  = tid >> 5;
    const int lane = tid & 31;
    const int m0   = blockIdx.x * 128;
    const int wr   = wid * 16;

    // resident A: read z fp32, convert to fp16 in smem (528B row stride)
    for (int idx = tid; idx < 8192; idx += 256) {
        int row = idx >> 6, c4 = idx & 63;
        float4 v = *(const float4*)(z + (size_t)(m0 + row) * DIM + c4 * 4);
        uint2 h;
        h.x = h2_as_u32(__floats2half2_rn(v.x, v.y));
        h.y = h2_as_u32(__floats2half2_rn(v.z, v.w));
        *(uint2*)(smem + SM_A + row * 528 + c4 * 8) = h;
    }

    // prologue: B chunk 0 + enorm chunk 0 -> buf 0
    for (int idx = tid; idx < 1024; idx += 256) {
        int row = idx >> 5, c16 = idx & 31;
        cp16(sb + SM_B + row * 528 + c16 * 16, g_eh + (size_t)row * DIM + c16 * 8);
    }
    if (tid < 8) cp16(sb + SM_EN + tid * 16, g_half_enorm + tid * 4);
    CP_COMMIT();
    CP_WAIT0();
    __syncthreads();

    const uint32_t Abase = sb + SM_A + (uint32_t)(wr + (lane & 15)) * 528
                         + (uint32_t)(lane >> 4) * 16;
    const uint32_t Blane = (uint32_t)lane * 528;
    const int tg = lane & 3;

    float b1a = -FLT_MAX, b2a = -FLT_MAX, b1b = -FLT_MAX, b2b = -FLT_MAX;
    int   bia = 0, bib = 0;

    int buf = 0;
    for (int c = 0; c < NITER; c++) {
        if (c + 1 < NITER) {
            const int n0n = (c + 1) * BN;
            const uint32_t db = sb + SM_B + (buf ^ 1) * B_TILE;
            for (int idx = tid; idx < 1024; idx += 256) {
                int row = idx >> 5, c16 = idx & 31;
                cp16(db + row * 528 + c16 * 16, g_eh + (size_t)(n0n + row) * DIM + c16 * 8);
            }
            if (tid < 8)
                cp16(sb + SM_EN + (buf ^ 1) * 128 + tid * 16, g_half_enorm + n0n + tid * 4);
            CP_COMMIT();
        }

        float acc[4][4];
        #pragma unroll
        for (int n = 0; n < 4; n++)
            #pragma unroll
            for (int r = 0; r < 4; r++) acc[n][r] = 0.f;

        const uint32_t B0 = sb + SM_B + buf * B_TILE + Blane;

        #pragma unroll
        for (int ks = 0; ks < 16; ks++) {
            const uint32_t off = ks * 32;
            uint32_t a[4], p0[4], p1[4];
            ldsm4(a, Abase + off);
            ldsm4(p0, B0 + off);
            ldsm4(p1, B0 + off + 16);
            #pragma unroll
            for (int n = 0; n < 4; n++) mma_f16(acc[n], a, p0[n], p1[n]);
        }

        // epilogue: top-2 per row (enorm from staged smem buffer)
        const int n0 = c * BN;
        const float* en = (const float*)(smem + SM_EN + buf * 128);
        #pragma unroll
        for (int n = 0; n < 4; n++) {
            const int lc = n * 8 + tg * 2;
            const float e0 = en[lc], e1 = en[lc + 1];
            float s;
            s = acc[n][0] - e0;
            if (s > b1a) { b2a = b1a; b1a = s; bia = n0 + lc; } else if (s > b2a) b2a = s;
            s = acc[n][1] - e1;
            if (s > b1a) { b2a = b1a; b1a = s; bia = n0 + lc + 1; } else if (s > b2a) b2a = s;
            s = acc[n][2] - e0;
            if (s > b1b) { b2b = b1b; b1b = s; bib = n0 + lc; } else if (s > b2b) b2b = s;
            s = acc[n][3] - e1;
            if (s > b1b) { b2b = b1b; b1b = s; bib = n0 + lc + 1; } else if (s > b2b) b2b = s;
        }

        if (c + 1 < NITER) CP_WAIT0();
        __syncthreads();
        buf ^= 1;
    }

    // reduce across quad (4 threads share rows)
    #pragma unroll
    for (int o = 1; o <= 2; o <<= 1) {
        float ov1 = __shfl_xor_sync(0xffffffffu, b1a, o);
        float ov2 = __shfl_xor_sync(0xffffffffu, b2a, o);
        int   oi  = __shfl_xor_sync(0xffffffffu, bia, o);
        merge2(b1a, b2a, bia, ov1, ov2, oi);
        ov1 = __shfl_xor_sync(0xffffffffu, b1b, o);
        ov2 = __shfl_xor_sync(0xffffffffu, b2b, o);
        oi  = __shfl_xor_sync(0xffffffffu, bib, o);
        merge2(b1b, b2b, bib, ov1, ov2, oi);
    }

    if (tg == 0) {
        const int r0 = wr + (lane >> 2), r1 = r0 + 8;
        ((int*)(smem + SM_BEST))[r0] = bia;
        ((int*)(smem + SM_BEST))[r1] = bib;
        if (out_idx) { out_idx[m0 + r0] = (float)bia; out_idx[m0 + r1] = (float)bib; }
        if (b1a - b2a < THETA) {
            int s = atomicAdd(&g_rescue_count, 1);
            g_rescue_list[s] = m0 + r0;
            g_best[s] = 0ULL;
        }
        if (b1b - b2b < THETA) {
            int s = atomicAdd(&g_rescue_count, 1);
            g_rescue_list[s] = m0 + r1;
            g_best[s] = 0ULL;
        }
    }
    __syncthreads();

    // gather winning embedding rows (fp32, coalesced)
    const int* sbest = (const int*)(smem + SM_BEST);
    for (int i4 = tid; i4 < 128 * (DIM / 4); i4 += 256) {
        int r = i4 >> 6, cc = i4 & 63;
        int code = sbest[r];
        ((float4*)out_q)[(size_t)(m0 + r) * (DIM / 4) + cc] =
            ((const float4*)e)[(size_t)code * (DIM / 4) + cc];
    }
}

// ---------------------------------------------------------------------------
// 2-D exact fp32 rescue: block = (token-group of 8) x (code slice of 256)
// 1 code per thread; block-reduce; publish via packed atomicMax
// ---------------------------------------------------------------------------
__global__ void rescue_kernel(const float* __restrict__ z, const float* __restrict__ e)
{
    __shared__ float sz[8][260];
    __shared__ unsigned long long wb[8][8];   // [warp][token]
    const int tid = threadIdx.x;
    const int wid = tid >> 5;
    const int lane = tid & 31;
    const int cnt = g_rescue_count;
    const int ngroups = (cnt + 7) >> 3;

    for (int p = blockIdx.x; p < ngroups * NSLICE; p += gridDim.x) {
        const int grp = p / NSLICE;
        const int slice = p - grp * NSLICE;
        const int base = grp * 8;
        const int nt = min(8, cnt - base);
        __syncthreads();
        for (int i = tid; i < nt * DIM; i += 256) {
            int t = i >> 8, k = i & 255;
            sz[t][k] = z[(size_t)g_rescue_list[base + t] * DIM + k];
        }
        __syncthreads();

        const int code = slice * (NCODES / NSLICE) + tid;
        const float4* er = (const float4*)(e + (size_t)code * DIM);
        float acc[8];
        #pragma unroll
        for (int t = 0; t < 8; t++) acc[t] = 0.f;
        #pragma unroll 8
        for (int k4 = 0; k4 < DIM / 4; k4++) {
            float4 v = __ldg(er + k4);
            #pragma unroll
            for (int t = 0; t < 8; t++) {
                float4 zv = *(const float4*)&sz[t][4 * k4];
                acc[t] += zv.x * v.x + zv.y * v.y + zv.z * v.z + zv.w * v.w;
            }
        }
        const float he = g_half_enorm[code];
        unsigned long long bk[8];
        #pragma unroll
        for (int t = 0; t < 8; t++) {
            float s = acc[t] - he;
            bk[t] = ((unsigned long long)f2u_ord(s) << 32) | (uint32_t)(4095 - code);
        }

        // warp reduce
        #pragma unroll
        for (int o = 16; o; o >>= 1) {
            #pragma unroll
            for (int t = 0; t < 8; t++) {
                unsigned long long ok = __shfl_xor_sync(0xffffffffu, bk[t], o);
                if (ok > bk[t]) bk[t] = ok;
            }
        }
        if (lane == 0) {
            #pragma unroll
            for (int t = 0; t < 8; t++) wb[wid][t] = bk[t];
        }
        __syncthreads();
        if (tid < 8 && tid < nt) {
            unsigned long long m = wb[0][tid];
            #pragma unroll
            for (int w = 1; w < 8; w++) if (wb[w][tid] > m) m = wb[w][tid];
            atomicMax(&g_best[base + tid], m);
        }
    }
}

// ---------------------------------------------------------------------------
// fixup: decode winners, write indices, gather rows. 64 threads/block.
// ---------------------------------------------------------------------------
__global__ void fixup_kernel(const float* __restrict__ e,
                             float* __restrict__ out_q, float* __restrict__ out_idx)
{
    const int cnt = g_rescue_count;
    for (int s = blockIdx.x; s < cnt; s += gridDim.x) {
        const int tok = g_rescue_list[s];
        const int code = 4095 - (int)(uint32_t)(g_best[s] & 0xFFFFFFFFULL);
        if (threadIdx.x == 0 && out_idx) out_idx[tok] = (float)code;
        ((float4*)out_q)[(size_t)tok * (DIM / 4) + threadIdx.x] =
            ((const float4*)e)[(size_t)code * (DIM / 4) + threadIdx.x];
    }
}

// ---------------------------------------------------------------------------
extern "C" void kernel_launch(void* const* d_in, const int* in_sizes, int n_in,
                              void* d_out, int out_size)
{
    const float* z = (const float*)d_in[0];
    const float* e = (const float*)d_in[1];
    if (n_in >= 2 && in_sizes[0] == NCODES * DIM && in_sizes[1] == N_TOKENS * DIM) {
        const float* t = z; z = e; e = t;
    }

    float* out = (float*)d_out;
    float* out_idx = (out_size >= N_TOKENS * DIM + N_TOKENS)
                         ? (out + (size_t)N_TOKENS * DIM)
                         : nullptr;

    cudaFuncSetAttribute(vq_kernel, cudaFuncAttributeMaxDynamicSharedMemorySize, SMEM_TOTAL);

    convert_kernel<<<256, 256>>>(e);
    enorm_kernel<<<NCODES / 8, 256>>>(e);
    vq_kernel<<<N_TOKENS / 128, 256, SMEM_TOTAL>>>(z, e, out, out_idx);
    rescue_kernel<<<2048, 256>>>(z, e);
    fixup_kernel<<<512, 64>>>(e, out, out_idx);
}